// round 1
// baseline (speedup 1.0000x reference)
#include <cuda_runtime.h>
#include <math.h>

#define Bb 4
#define Hh 480
#define Wd 640
#define HW (Hh * Wd)
#define N_PIX (Bb * HW)

// Precomputed per-pixel, per-tap sampling tables (loop-invariant across the 18 iterations)
__device__ float d_PY[9 * N_PIX];   // absolute sample y coord per tap
__device__ float d_PX[9 * N_PIX];   // absolute sample x coord per tap
__device__ float d_WW[9 * N_PIX];   // aff_k * (1 - mask_fix)  (fold post-mix scale into tap weight)
__device__ float d_CONF[N_PIX];     // per-pixel confidence multiplier for next-iter g
__device__ float d_ADD[N_PIX];      // mask_fix * feat_fix  (fixed-point injection constant)
__device__ float d_G[2][N_PIX];     // ping-pong propagated field g = f * conf

__global__ void __launch_bounds__(256)
precompute_kernel(const float* __restrict__ feat_init,
                  const float* __restrict__ guidance,
                  const float* __restrict__ confidence,
                  const float* __restrict__ feat_fix,
                  const float* __restrict__ aff_scale)
{
    int idx = blockIdx.x * blockDim.x + threadIdx.x;
    if (idx >= N_PIX) return;
    int b   = idx / HW;
    int rem = idx - b * HW;
    int y   = rem / Wd;
    int x   = rem - y * Wd;

    const float* gb = guidance + (size_t)b * 24 * HW + rem;
    float inv_scale = 1.0f / (aff_scale[0] + 1e-8f);

    // affinity normalization
    float a[8];
    float s = 1e-4f;
#pragma unroll
    for (int j = 0; j < 8; j++) {
        a[j] = tanhf(gb[(16 + j) * HW]) * inv_scale;
        s += fabsf(a[j]);
    }
    s = fmaxf(s, 1.0f);
    float inv_s = 1.0f / s;
    float sum8 = 0.0f;
#pragma unroll
    for (int j = 0; j < 8; j++) { a[j] *= inv_s; sum8 += a[j]; }
    float aref = 1.0f - sum8;

    float fix  = feat_fix[idx];
    bool  m    = fix > 0.0f;
    float conf = m ? 1.0f : confidence[idx];
    float sp   = m ? 0.0f : 1.0f;   // (1 - mask_fix)
    float cp   = m ? fix  : 0.0f;   // mask_fix * feat_fix

    const int ky[9] = {-1, -1, -1, 0, 0, 0, 1, 1, 1};
    const int kx[9] = {-1,  0,  1,-1, 0, 1,-1, 0, 1};

#pragma unroll
    for (int k = 0; k < 9; k++) {
        float dy, dx, af;
        if (k < 4)       { dy = gb[(2 * k) * HW];       dx = gb[(2 * k + 1) * HW];       af = a[k];     }
        else if (k == 4) { dy = 0.0f;                   dx = 0.0f;                        af = aref;     }
        else             { dy = gb[(2 * (k - 1)) * HW]; dx = gb[(2 * (k - 1) + 1) * HW]; af = a[k - 1]; }
        d_PY[k * N_PIX + idx] = (float)(y + ky[k]) + dy;
        d_PX[k * N_PIX + idx] = (float)(x + kx[k]) + dx;
        d_WW[k * N_PIX + idx] = af * sp;
    }
    d_CONF[idx] = conf;
    d_ADD[idx]  = cp;

    // g_0 = ((1-m)*feat_init + m*fix) * conf
    float f0 = fmaf(sp, feat_init[idx], cp);
    d_G[0][idx] = f0 * conf;
}

__global__ void __launch_bounds__(256)
prop_kernel(int src, float* __restrict__ out_ext, int last)
{
    int idx = blockIdx.x * blockDim.x + threadIdx.x;
    if (idx >= N_PIX) return;
    int b = idx / HW;
    const float* __restrict__ img = &d_G[src][b * HW];

    float acc = 0.0f;
#pragma unroll
    for (int k = 0; k < 9; k++) {
        float py = d_PY[k * N_PIX + idx];
        float px = d_PX[k * N_PIX + idx];
        float w  = d_WW[k * N_PIX + idx];

        float y0f = floorf(py), x0f = floorf(px);
        float wy = py - y0f;
        float wx = px - x0f;
        int y0 = (int)y0f, x0 = (int)x0f;
        int y1 = y0 + 1,   x1 = x0 + 1;

        bool vy0 = (y0 >= 0) & (y0 < Hh);
        bool vy1 = (y1 >= 0) & (y1 < Hh);
        bool vx0 = (x0 >= 0) & (x0 < Wd);
        bool vx1 = (x1 >= 0) & (x1 < Wd);

        int yc0 = min(max(y0, 0), Hh - 1);
        int yc1 = min(max(y1, 0), Hh - 1);
        int xc0 = min(max(x0, 0), Wd - 1);
        int xc1 = min(max(x1, 0), Wd - 1);

        float v00 = (vy0 & vx0) ? img[yc0 * Wd + xc0] : 0.0f;
        float v01 = (vy0 & vx1) ? img[yc0 * Wd + xc1] : 0.0f;
        float v10 = (vy1 & vx0) ? img[yc1 * Wd + xc0] : 0.0f;
        float v11 = (vy1 & vx1) ? img[yc1 * Wd + xc1] : 0.0f;

        float s0 = fmaf(wx, v01 - v00, v00);
        float s1 = fmaf(wx, v11 - v10, v10);
        float samp = fmaf(wy, s1 - s0, s0);
        acc = fmaf(w, samp, acc);
    }

    float f = acc + d_ADD[idx];
    if (last) {
        out_ext[idx] = f;
    } else {
        d_G[src ^ 1][idx] = f * d_CONF[idx];
    }
}

extern "C" void kernel_launch(void* const* d_in, const int* in_sizes, int n_in,
                              void* d_out, int out_size)
{
    const float* feat_init  = (const float*)d_in[0];
    const float* guidance   = (const float*)d_in[1];
    const float* confidence = (const float*)d_in[2];
    const float* feat_fix   = (const float*)d_in[3];
    const float* aff_scale  = (const float*)d_in[4];
    float* out = (float*)d_out;

    const int threads = 256;
    const int blocks  = (N_PIX + threads - 1) / threads;

    precompute_kernel<<<blocks, threads>>>(feat_init, guidance, confidence, feat_fix, aff_scale);

    // 18 propagation iterations, ping-pong between d_G[0]/d_G[1]; last writes f (no conf fold)
    for (int t = 0; t < 18; t++) {
        int last = (t == 17) ? 1 : 0;
        prop_kernel<<<blocks, threads>>>(t & 1, out, last);
    }
}